// round 4
// baseline (speedup 1.0000x reference)
#include <cuda_runtime.h>

// CapsuleLayer dynamic routing, fully fused. C=10,B=128,N=1152,IN=8,OUT=16.
// One CTA per (c, batch-pair), 288 threads, 2 CTAs resident per SM so the
// L2-bound priors GEMM of one CTA overlaps the LDS/shuffle-bound routing of
// the other. Thread t owns 4 route-node pairs: r=0 in registers, r=1..3 in
// shared memory. Logits are 8 thread-local registers.

#define CCAP   10
#define BD     128
#define ND     1152
#define OUTD   16
#define THREADS 288
#define NW      9
#define SROWS   864                        // smem-resident rows per batch
#define NBLOCKS (CCAP * BD / 2)            // 640

// shared memory layout (floats)
#define PRI_SZ    (2 * 16 * SROWS)         // 27648 : pri_s[bb][o][row']
#define VRED_OFF  PRI_SZ
#define VRED_SZ   (NW * 32)                // 288
#define SPRED_OFF (VRED_OFF + VRED_SZ)
#define WMAX_OFF  (SPRED_OFF + 2 * NW)
#define OUTV_OFF  (WMAX_OFF + 2 * NW)
#define SMEM_FLOATS (OUTV_OFF + 32)
#define SMEM_BYTES  (SMEM_FLOATS * 4)      // 112,016 B

__global__ __launch_bounds__(THREADS, 2)
void caps_routing_kernel(const float* __restrict__ x,
                         const float* __restrict__ W,
                         float* __restrict__ out)
{
    extern __shared__ float sm[];
    float* pri_s = sm;                 // [2][16][SROWS]
    float* vred  = sm + VRED_OFF;      // [9][32]
    float* spred = sm + SPRED_OFF;     // [9][2]
    float* wmax  = sm + WMAX_OFF;      // [9][2]
    float* outv  = sm + OUTV_OFF;      // [2][16]

    const int tid  = threadIdx.x;
    const int lane = tid & 31;
    const int w    = tid >> 5;           // 0..8
    const int c    = blockIdx.x >> 6;
    const int b0   = (blockIdx.x & 63) * 2;

    const float4* __restrict__ X4 = (const float4*)x;
    const float4* __restrict__ W4 = (const float4*)W;

    // ---------------- Phase A: priors (4 row-pairs per thread) ----------------
    float priA0[16], priA1[16];

    #pragma unroll
    for (int r = 0; r < 4; r++) {
        const int n = tid + r * THREADS;
        float4 x00 = X4[((size_t)b0 * ND + n) * 2 + 0];
        float4 x01 = X4[((size_t)b0 * ND + n) * 2 + 1];
        float4 x10 = X4[((size_t)(b0 + 1) * ND + n) * 2 + 0];
        float4 x11 = X4[((size_t)(b0 + 1) * ND + n) * 2 + 1];
        float xa[8] = {x00.x, x00.y, x00.z, x00.w, x01.x, x01.y, x01.z, x01.w};
        float xb[8] = {x10.x, x10.y, x10.z, x10.w, x11.x, x11.y, x11.z, x11.w};

        float acc0[16], acc1[16];
        #pragma unroll
        for (int o = 0; o < 16; o++) { acc0[o] = 0.f; acc1[o] = 0.f; }

        const float4* wp = W4 + ((size_t)c * ND + n) * 32;  // 8*16 floats
        #pragma unroll
        for (int i = 0; i < 8; i++) {
            const float va = xa[i], vb = xb[i];
            #pragma unroll
            for (int q = 0; q < 4; q++) {
                float4 wv = wp[i * 4 + q];
                acc0[4*q+0] += va * wv.x; acc0[4*q+1] += va * wv.y;
                acc0[4*q+2] += va * wv.z; acc0[4*q+3] += va * wv.w;
                acc1[4*q+0] += vb * wv.x; acc1[4*q+1] += vb * wv.y;
                acc1[4*q+2] += vb * wv.z; acc1[4*q+3] += vb * wv.w;
            }
        }
        if (r == 0) {
            #pragma unroll
            for (int o = 0; o < 16; o++) { priA0[o] = acc0[o]; priA1[o] = acc1[o]; }
        } else {
            const int j = (r - 1) * THREADS + tid;
            #pragma unroll
            for (int o = 0; o < 16; o++) {
                pri_s[o * SROWS + j]        = acc0[o];   // bb=0
                pri_s[(16 + o) * SROWS + j] = acc1[o];   // bb=1
            }
        }
    }
    __syncthreads();

    const float* __restrict__ p0 = pri_s + tid;              // + o*SROWS + (r-1)*288
    const float* __restrict__ p1 = pri_s + 16 * SROWS + tid;

    float lg0[4] = {0.f, 0.f, 0.f, 0.f};
    float lg1[4] = {0.f, 0.f, 0.f, 0.f};

    // ---------------- Phase B: 3 routing iterations ----------------
    #pragma unroll 1
    for (int it = 0; it < 3; it++) {
        // --- per-batch block max of logits ---
        float m0 = fmaxf(fmaxf(lg0[0], lg0[1]), fmaxf(lg0[2], lg0[3]));
        float m1 = fmaxf(fmaxf(lg1[0], lg1[1]), fmaxf(lg1[2], lg1[3]));
        #pragma unroll
        for (int d = 16; d; d >>= 1) {
            m0 = fmaxf(m0, __shfl_xor_sync(0xffffffffu, m0, d));
            m1 = fmaxf(m1, __shfl_xor_sync(0xffffffffu, m1, d));
        }
        if (lane == 0) { wmax[w * 2] = m0; wmax[w * 2 + 1] = m1; }
        __syncthreads();
        m0 = wmax[0]; m1 = wmax[1];
        #pragma unroll
        for (int j = 1; j < NW; j++) {
            m0 = fmaxf(m0, wmax[j * 2]);
            m1 = fmaxf(m1, wmax[j * 2 + 1]);
        }

        // --- exp + weighted accumulation ---
        float e0[4], e1[4];
        #pragma unroll
        for (int r = 0; r < 4; r++) {
            e0[r] = __expf(lg0[r] - m0);
            e1[r] = __expf(lg1[r] - m1);
        }
        float sp0 = e0[0] + e0[1] + e0[2] + e0[3];
        float sp1 = e1[0] + e1[1] + e1[2] + e1[3];

        float v0[16], v1[16];
        #pragma unroll
        for (int o = 0; o < 16; o++) {
            v0[o] = e0[0] * priA0[o] + e0[1] * p0[o * SROWS]
                  + e0[2] * p0[o * SROWS + THREADS]
                  + e0[3] * p0[o * SROWS + 2 * THREADS];
            v1[o] = e1[0] * priA1[o] + e1[1] * p1[o * SROWS]
                  + e1[2] * p1[o * SROWS + THREADS]
                  + e1[3] * p1[o * SROWS + 2 * THREADS];
        }

        // batch-merging component-splitting warp reduce (31 shfl).
        float v[16];
        #pragma unroll
        for (int k = 0; k < 16; k++) {
            float s = (lane & 16) ? v0[k] : v1[k];
            float rr = __shfl_xor_sync(0xffffffffu, s, 16);
            v[k] = ((lane & 16) ? v1[k] : v0[k]) + rr;
        }
        #pragma unroll
        for (int k = 0; k < 8; k++) {
            float s = (lane & 8) ? v[k] : v[k + 8];
            float rr = __shfl_xor_sync(0xffffffffu, s, 8);
            v[k] = ((lane & 8) ? v[k + 8] : v[k]) + rr;
        }
        #pragma unroll
        for (int k = 0; k < 4; k++) {
            float s = (lane & 4) ? v[k] : v[k + 4];
            float rr = __shfl_xor_sync(0xffffffffu, s, 4);
            v[k] = ((lane & 4) ? v[k + 4] : v[k]) + rr;
        }
        #pragma unroll
        for (int k = 0; k < 2; k++) {
            float s = (lane & 2) ? v[k] : v[k + 2];
            float rr = __shfl_xor_sync(0xffffffffu, s, 2);
            v[k] = ((lane & 2) ? v[k + 2] : v[k]) + rr;
        }
        {
            float s = (lane & 1) ? v[0] : v[1];
            float rr = __shfl_xor_sync(0xffffffffu, s, 1);
            v[0] = ((lane & 1) ? v[1] : v[0]) + rr;
        }
        {   // sp: merge batches then butterfly
            float s = (lane & 16) ? sp0 : sp1;
            float rr = __shfl_xor_sync(0xffffffffu, s, 16);
            float sp = ((lane & 16) ? sp1 : sp0) + rr;
            #pragma unroll
            for (int d = 8; d; d >>= 1)
                sp += __shfl_xor_sync(0xffffffffu, sp, d);
            if ((lane & 15) == 0) spred[w * 2 + (lane >> 4)] = sp;
        }
        vred[w * 32 + lane] = v[0];
        __syncthreads();

        // --- final 9-way reduce + squash (warp 0: lanes 0-15 bb0, 16-31 bb1) ---
        if (tid < 32) {
            const int fb = tid >> 4;
            float O = 0.f, S = 0.f;
            #pragma unroll
            for (int j = 0; j < NW; j++) {
                O += vred[j * 32 + tid];
                S += spred[j * 2 + fb];
            }
            float t = O / S;
            float sq = t * t;
            #pragma unroll
            for (int d = 8; d; d >>= 1)
                sq += __shfl_xor_sync(0xffffffffu, sq, d);
            float scale = sq / ((1.f + sq) * sqrtf(sq + 1e-8f));
            float val = t * scale;
            outv[tid] = val;
            if (it == 2)
                out[((size_t)(c * BD + b0 + fb)) * OUTD + (tid & 15)] = val;
        }
        __syncthreads();

        // --- logit update: register + smem dot products ---
        if (it < 2) {
            float d00 = 0.f, d01 = 0.f, d02 = 0.f, d03 = 0.f;
            float d10 = 0.f, d11 = 0.f, d12 = 0.f, d13 = 0.f;
            #pragma unroll
            for (int o = 0; o < 16; o++) {
                const float o0 = outv[o];
                const float o1 = outv[16 + o];
                d00 += o0 * priA0[o];
                d01 += o0 * p0[o * SROWS];
                d02 += o0 * p0[o * SROWS + THREADS];
                d03 += o0 * p0[o * SROWS + 2 * THREADS];
                d10 += o1 * priA1[o];
                d11 += o1 * p1[o * SROWS];
                d12 += o1 * p1[o * SROWS + THREADS];
                d13 += o1 * p1[o * SROWS + 2 * THREADS];
            }
            lg0[0] += d00; lg0[1] += d01; lg0[2] += d02; lg0[3] += d03;
            lg1[0] += d10; lg1[1] += d11; lg1[2] += d12; lg1[3] += d13;
        }
    }
}

extern "C" void kernel_launch(void* const* d_in, const int* in_sizes, int n_in,
                              void* d_out, int out_size)
{
    const float* x = (const float*)d_in[0];
    const float* W = (const float*)d_in[1];
    // defensive: identify by size (x: 1,179,648 ; W: 1,474,560)
    if (n_in >= 2 && in_sizes[0] == CCAP * ND * 8 * OUTD) {
        x = (const float*)d_in[1];
        W = (const float*)d_in[0];
    }
    float* out = (float*)d_out;

    cudaFuncSetAttribute(caps_routing_kernel,
                         cudaFuncAttributeMaxDynamicSharedMemorySize, SMEM_BYTES);
    caps_routing_kernel<<<NBLOCKS, THREADS, SMEM_BYTES>>>(x, W, out);
}

// round 5
// speedup vs baseline: 2.5498x; 2.5498x over previous
#include <cuda_runtime.h>

// CapsuleLayer dynamic routing. C=10,B=128,N=1152,IN=8,OUT=16, 3 iters.
// Two kernels per launch:
//   1) transpose W -> Wt4[c][j][n]  (j = float4 group 0..31, n innermost)
//      so phase-A weight loads are perfectly coalesced (4 lines / LDG.128
//      instead of 32 -> 8x fewer l1tex wavefronts).
//   2) fused priors + routing, one CTA per (c, batch-pair), 576 threads,
//      priors split registers/smem, logits thread-local, shuffle reductions.

#define CCAP   10
#define BD     128
#define ND     1152
#define OUTD   16
#define HALF   576
#define THREADS 576
#define NWARPS  18
#define NBLOCKS (CCAP * BD / 2)   // 640

// transposed weights scratch: 10*32*1152 float4 = 5.9 MB
__device__ float4 g_Wt[CCAP * 32 * ND];

__global__ void transpose_W_kernel(const float4* __restrict__ W4)
{
    // dst index: ((c*32 + j)*ND + n), n fastest -> coalesced writes
    int idx = blockIdx.x * blockDim.x + threadIdx.x;
    if (idx >= CCAP * 32 * ND) return;
    int n  = idx % ND;
    int t  = idx / ND;
    int j  = t % 32;
    int c  = t / 32;
    g_Wt[idx] = W4[((size_t)c * ND + n) * 32 + j];
}

// shared memory layout (floats)
#define PRI_SZ    (2 * 16 * HALF)          // 18432 : pri_s[bb][o][n]
#define VRED_OFF  PRI_SZ
#define VRED_SZ   (NWARPS * 32)
#define SPRED_OFF (VRED_OFF + VRED_SZ)
#define WMAX_OFF  (SPRED_OFF + 2 * NWARPS)
#define OUTV_OFF  (WMAX_OFF + 2 * NWARPS)
#define SMEM_FLOATS (OUTV_OFF + 32)
#define SMEM_BYTES  (SMEM_FLOATS * 4)      // ~76.3 KB

__global__ __launch_bounds__(THREADS, 1)
void caps_routing_kernel(const float* __restrict__ x,
                         float* __restrict__ out)
{
    extern __shared__ float sm[];
    float* pri_s = sm;                 // [2][16][HALF]
    float* vred  = sm + VRED_OFF;      // [18][32]
    float* spred = sm + SPRED_OFF;     // [18][2]
    float* wmax  = sm + WMAX_OFF;      // [18][2]
    float* outv  = sm + OUTV_OFF;      // [2][16]

    const int tid  = threadIdx.x;
    const int lane = tid & 31;
    const int w    = tid >> 5;           // 0..17
    const int c    = blockIdx.x >> 6;
    const int b0   = (blockIdx.x & 63) * 2;

    const float4* __restrict__ X4 = (const float4*)x;

    // ---------------- Phase A: priors ----------------
    float priA0[16], priA1[16];
    float la0 = 0.f, la1 = 0.f, lb0 = 0.f, lb1 = 0.f;  // logits

    #pragma unroll
    for (int rep = 0; rep < 2; rep++) {
        const int n = tid + rep * HALF;
        float4 x00 = X4[((size_t)b0 * ND + n) * 2 + 0];
        float4 x01 = X4[((size_t)b0 * ND + n) * 2 + 1];
        float4 x10 = X4[((size_t)(b0 + 1) * ND + n) * 2 + 0];
        float4 x11 = X4[((size_t)(b0 + 1) * ND + n) * 2 + 1];
        float xa[8] = {x00.x, x00.y, x00.z, x00.w, x01.x, x01.y, x01.z, x01.w};
        float xb[8] = {x10.x, x10.y, x10.z, x10.w, x11.x, x11.y, x11.z, x11.w};

        float acc0[16], acc1[16];
        #pragma unroll
        for (int o = 0; o < 16; o++) { acc0[o] = 0.f; acc1[o] = 0.f; }

        // coalesced: lane -> n consecutive, stride ND between j's
        const float4* wp = g_Wt + (size_t)c * 32 * ND + n;
        #pragma unroll
        for (int i = 0; i < 8; i++) {
            const float va = xa[i], vb = xb[i];
            #pragma unroll
            for (int q = 0; q < 4; q++) {
                float4 wv = wp[(size_t)(i * 4 + q) * ND];
                acc0[4*q+0] += va * wv.x; acc0[4*q+1] += va * wv.y;
                acc0[4*q+2] += va * wv.z; acc0[4*q+3] += va * wv.w;
                acc1[4*q+0] += vb * wv.x; acc1[4*q+1] += vb * wv.y;
                acc1[4*q+2] += vb * wv.z; acc1[4*q+3] += vb * wv.w;
            }
        }
        if (rep == 0) {
            #pragma unroll
            for (int o = 0; o < 16; o++) { priA0[o] = acc0[o]; priA1[o] = acc1[o]; }
        } else {
            #pragma unroll
            for (int o = 0; o < 16; o++) {
                pri_s[o * HALF + tid]        = acc0[o];   // bb=0
                pri_s[(16 + o) * HALF + tid] = acc1[o];   // bb=1
            }
        }
    }
    __syncthreads();

    const float* __restrict__ prow0 = pri_s + tid;              // + o*HALF (bb=0)
    const float* __restrict__ prow1 = pri_s + 16 * HALF + tid;  // + o*HALF (bb=1)

    // ---------------- Phase B: 3 routing iterations ----------------
    #pragma unroll 1
    for (int it = 0; it < 3; it++) {
        // --- per-batch block max of logits ---
        float m0 = fmaxf(la0, lb0);
        float m1 = fmaxf(la1, lb1);
        #pragma unroll
        for (int d = 16; d; d >>= 1) {
            m0 = fmaxf(m0, __shfl_xor_sync(0xffffffffu, m0, d));
            m1 = fmaxf(m1, __shfl_xor_sync(0xffffffffu, m1, d));
        }
        if (lane == 0) { wmax[w * 2] = m0; wmax[w * 2 + 1] = m1; }
        __syncthreads();
        m0 = wmax[0]; m1 = wmax[1];
        #pragma unroll
        for (int j = 1; j < NWARPS; j++) {
            m0 = fmaxf(m0, wmax[j * 2]);
            m1 = fmaxf(m1, wmax[j * 2 + 1]);
        }

        // --- exp + weighted accumulation ---
        float ea0 = __expf(la0 - m0), ea1 = __expf(la1 - m1);
        float eb0 = __expf(lb0 - m0), eb1 = __expf(lb1 - m1);
        float sp0 = ea0 + eb0, sp1 = ea1 + eb1;

        float v0[16], v1[16];
        #pragma unroll
        for (int o = 0; o < 16; o++) {
            v0[o] = ea0 * priA0[o] + eb0 * prow0[o * HALF];
            v1[o] = ea1 * priA1[o] + eb1 * prow1[o * HALF];
        }

        // batch-merging component-splitting warp reduce (31 shfl):
        // bit-16 merges batches; bits 8/4/2/1 split components.
        float v[16];
        #pragma unroll
        for (int k = 0; k < 16; k++) {
            float s = (lane & 16) ? v0[k] : v1[k];
            float r = __shfl_xor_sync(0xffffffffu, s, 16);
            v[k] = ((lane & 16) ? v1[k] : v0[k]) + r;
        }
        #pragma unroll
        for (int k = 0; k < 8; k++) {
            float s = (lane & 8) ? v[k] : v[k + 8];
            float r = __shfl_xor_sync(0xffffffffu, s, 8);
            v[k] = ((lane & 8) ? v[k + 8] : v[k]) + r;
        }
        #pragma unroll
        for (int k = 0; k < 4; k++) {
            float s = (lane & 4) ? v[k] : v[k + 4];
            float r = __shfl_xor_sync(0xffffffffu, s, 4);
            v[k] = ((lane & 4) ? v[k + 4] : v[k]) + r;
        }
        #pragma unroll
        for (int k = 0; k < 2; k++) {
            float s = (lane & 2) ? v[k] : v[k + 2];
            float r = __shfl_xor_sync(0xffffffffu, s, 2);
            v[k] = ((lane & 2) ? v[k + 2] : v[k]) + r;
        }
        {
            float s = (lane & 1) ? v[0] : v[1];
            float r = __shfl_xor_sync(0xffffffffu, s, 1);
            v[0] = ((lane & 1) ? v[1] : v[0]) + r;
        }
        {   // sp: merge batches then butterfly
            float s = (lane & 16) ? sp0 : sp1;
            float r = __shfl_xor_sync(0xffffffffu, s, 16);
            float sp = ((lane & 16) ? sp1 : sp0) + r;
            #pragma unroll
            for (int d = 8; d; d >>= 1)
                sp += __shfl_xor_sync(0xffffffffu, sp, d);
            if ((lane & 15) == 0) spred[w * 2 + (lane >> 4)] = sp;
        }
        vred[w * 32 + lane] = v[0];
        __syncthreads();

        // --- final 18-way reduce + squash (warp 0: lanes 0-15 bb0, 16-31 bb1) ---
        if (tid < 32) {
            const int fb = tid >> 4;
            float O = 0.f, S = 0.f;
            #pragma unroll
            for (int j = 0; j < NWARPS; j++) {
                O += vred[j * 32 + tid];
                S += spred[j * 2 + fb];
            }
            float t = O / S;
            float sq = t * t;
            #pragma unroll
            for (int d = 8; d; d >>= 1)
                sq += __shfl_xor_sync(0xffffffffu, sq, d);
            float scale = sq / ((1.f + sq) * sqrtf(sq + 1e-8f));
            float val = t * scale;
            outv[tid] = val;
            if (it == 2)
                out[((size_t)(c * BD + b0 + fb)) * OUTD + (tid & 15)] = val;
        }
        __syncthreads();

        // --- logit update: register dot products ---
        if (it < 2) {
            float da0 = 0.f, da1 = 0.f, db0 = 0.f, db1 = 0.f;
            #pragma unroll
            for (int o = 0; o < 16; o++) {
                const float o0 = outv[o];        // LDS broadcast
                const float o1 = outv[16 + o];
                da0 += o0 * priA0[o];
                da1 += o1 * priA1[o];
                db0 += o0 * prow0[o * HALF];
                db1 += o1 * prow1[o * HALF];
            }
            la0 += da0; la1 += da1; lb0 += db0; lb1 += db1;
        }
    }
}

extern "C" void kernel_launch(void* const* d_in, const int* in_sizes, int n_in,
                              void* d_out, int out_size)
{
    const float* x = (const float*)d_in[0];
    const float* W = (const float*)d_in[1];
    // defensive: identify by size (x: 1,179,648 ; W: 1,474,560)
    if (n_in >= 2 && in_sizes[0] == CCAP * ND * 8 * OUTD) {
        x = (const float*)d_in[1];
        W = (const float*)d_in[0];
    }
    float* out = (float*)d_out;

    const int ttotal = CCAP * 32 * ND;
    transpose_W_kernel<<<(ttotal + 255) / 256, 256>>>((const float4*)W);

    cudaFuncSetAttribute(caps_routing_kernel,
                         cudaFuncAttributeMaxDynamicSharedMemorySize, SMEM_BYTES);
    caps_routing_kernel<<<NBLOCKS, THREADS, SMEM_BYTES>>>(x, out);
}

// round 6
// speedup vs baseline: 2.6663x; 1.0457x over previous
#include <cuda_runtime.h>

// CapsuleLayer dynamic routing. C=10,B=128,N=1152,IN=8,OUT=16, 3 iters.
//   1) transpose W -> Wt4[c][j][n] (n innermost) : coalesced phase-A loads.
//   2) fused priors + routing, one CTA per (c, batch-pair), 576 threads.
// Routing uses shift-free softmax (exact: shift cancels; logits bounded ~40)
// which lets the logit-update sweep fuse into the accumulation sweep:
// 3 priors sweeps total instead of 5, no max reductions.
// Iteration 0 exploits logits==0 -> exactly uniform attention (S = N).

#define CCAP   10
#define BD     128
#define ND     1152
#define OUTD   16
#define HALF   576
#define THREADS 576
#define NWARPS  18
#define NBLOCKS (CCAP * BD / 2)   // 640

// transposed weights scratch: 10*32*1152 float4 = 5.9 MB
__device__ float4 g_Wt[CCAP * 32 * ND];

__global__ void transpose_W_kernel(const float4* __restrict__ W4)
{
    int idx = blockIdx.x * blockDim.x + threadIdx.x;
    if (idx >= CCAP * 32 * ND) return;
    int n  = idx % ND;
    int t  = idx / ND;
    int j  = t % 32;
    int c  = t / 32;
    g_Wt[idx] = W4[((size_t)c * ND + n) * 32 + j];
}

// shared memory layout (floats)
#define PRI_SZ    (2 * 16 * HALF)          // 18432 : pri_s[bb][o][n]
#define VRED_OFF  PRI_SZ
#define VRED_SZ   (NWARPS * 32)
#define SPRED_OFF (VRED_OFF + VRED_SZ)
#define OUTV_OFF  (SPRED_OFF + 2 * NWARPS)
#define SMEM_FLOATS (OUTV_OFF + 32)
#define SMEM_BYTES  (SMEM_FLOATS * 4)      // ~76.2 KB

__global__ __launch_bounds__(THREADS, 1)
void caps_routing_kernel(const float* __restrict__ x,
                         float* __restrict__ out)
{
    extern __shared__ float sm[];
    float* pri_s = sm;                 // [2][16][HALF]
    float* vred  = sm + VRED_OFF;      // [18][32]
    float* spred = sm + SPRED_OFF;     // [18][2]
    float* outv  = sm + OUTV_OFF;      // [2][16]

    const int tid  = threadIdx.x;
    const int lane = tid & 31;
    const int w    = tid >> 5;           // 0..17
    const int c    = blockIdx.x >> 6;
    const int b0   = (blockIdx.x & 63) * 2;

    const float4* __restrict__ X4 = (const float4*)x;

    // ---------------- Phase A: priors ----------------
    float priA0[16], priA1[16];

    #pragma unroll
    for (int rep = 0; rep < 2; rep++) {
        const int n = tid + rep * HALF;
        float4 x00 = X4[((size_t)b0 * ND + n) * 2 + 0];
        float4 x01 = X4[((size_t)b0 * ND + n) * 2 + 1];
        float4 x10 = X4[((size_t)(b0 + 1) * ND + n) * 2 + 0];
        float4 x11 = X4[((size_t)(b0 + 1) * ND + n) * 2 + 1];
        float xa[8] = {x00.x, x00.y, x00.z, x00.w, x01.x, x01.y, x01.z, x01.w};
        float xb[8] = {x10.x, x10.y, x10.z, x10.w, x11.x, x11.y, x11.z, x11.w};

        float acc0[16], acc1[16];
        #pragma unroll
        for (int o = 0; o < 16; o++) { acc0[o] = 0.f; acc1[o] = 0.f; }

        // coalesced: lane -> n consecutive, stride ND between j's
        const float4* wp = g_Wt + (size_t)c * 32 * ND + n;
        #pragma unroll
        for (int i = 0; i < 8; i++) {
            const float va = xa[i], vb = xb[i];
            #pragma unroll
            for (int q = 0; q < 4; q++) {
                float4 wv = wp[(size_t)(i * 4 + q) * ND];
                acc0[4*q+0] += va * wv.x; acc0[4*q+1] += va * wv.y;
                acc0[4*q+2] += va * wv.z; acc0[4*q+3] += va * wv.w;
                acc1[4*q+0] += vb * wv.x; acc1[4*q+1] += vb * wv.y;
                acc1[4*q+2] += vb * wv.z; acc1[4*q+3] += vb * wv.w;
            }
        }
        if (rep == 0) {
            #pragma unroll
            for (int o = 0; o < 16; o++) { priA0[o] = acc0[o]; priA1[o] = acc1[o]; }
        } else {
            #pragma unroll
            for (int o = 0; o < 16; o++) {
                pri_s[o * HALF + tid]        = acc0[o];   // bb=0
                pri_s[(16 + o) * HALF + tid] = acc1[o];   // bb=1
            }
        }
    }
    __syncthreads();

    const float* __restrict__ prow0 = pri_s + tid;              // + o*HALF (bb=0)
    const float* __restrict__ prow1 = pri_s + 16 * HALF + tid;  // + o*HALF (bb=1)

    // logits (shift-free): a = node rep0, b = node rep1; 0/1 = batch
    float la0 = 0.f, la1 = 0.f, lb0 = 0.f, lb1 = 0.f;

    // ---------------- Phase B: 3 fused routing sweeps ----------------
    #pragma unroll 1
    for (int it = 0; it < 3; it++) {
        float v0[16], v1[16];
        float sp0 = 0.f, sp1 = 0.f;

        if (it == 0) {
            // logits == 0: attention exactly uniform; S = ND (constant).
            #pragma unroll
            for (int o = 0; o < 16; o++) {
                v0[o] = priA0[o] + prow0[o * HALF];
                v1[o] = priA1[o] + prow1[o * HALF];
            }
        } else {
            // fused: logit update -> exp -> weighted accumulation, one sweep.
            // batch 0
            {
                float d = 0.f;
                #pragma unroll
                for (int o = 0; o < 16; o++) d += outv[o] * priA0[o];
                la0 += d;
                float e = __expf(la0);
                sp0 = e;
                #pragma unroll
                for (int o = 0; o < 16; o++) v0[o] = e * priA0[o];

                float p[16];
                #pragma unroll
                for (int o = 0; o < 16; o++) p[o] = prow0[o * HALF];
                d = 0.f;
                #pragma unroll
                for (int o = 0; o < 16; o++) d += outv[o] * p[o];
                lb0 += d;
                e = __expf(lb0);
                sp0 += e;
                #pragma unroll
                for (int o = 0; o < 16; o++) v0[o] += e * p[o];
            }
            // batch 1
            {
                float d = 0.f;
                #pragma unroll
                for (int o = 0; o < 16; o++) d += outv[16 + o] * priA1[o];
                la1 += d;
                float e = __expf(la1);
                sp1 = e;
                #pragma unroll
                for (int o = 0; o < 16; o++) v1[o] = e * priA1[o];

                float p[16];
                #pragma unroll
                for (int o = 0; o < 16; o++) p[o] = prow1[o * HALF];
                d = 0.f;
                #pragma unroll
                for (int o = 0; o < 16; o++) d += outv[16 + o] * p[o];
                lb1 += d;
                e = __expf(lb1);
                sp1 += e;
                #pragma unroll
                for (int o = 0; o < 16; o++) v1[o] += e * p[o];
            }
        }

        // batch-merging component-splitting warp reduce (31 shfl):
        // bit-16 merges batches; bits 8/4/2/1 split components.
        float v[16];
        #pragma unroll
        for (int k = 0; k < 16; k++) {
            float s = (lane & 16) ? v0[k] : v1[k];
            float r = __shfl_xor_sync(0xffffffffu, s, 16);
            v[k] = ((lane & 16) ? v1[k] : v0[k]) + r;
        }
        #pragma unroll
        for (int k = 0; k < 8; k++) {
            float s = (lane & 8) ? v[k] : v[k + 8];
            float r = __shfl_xor_sync(0xffffffffu, s, 8);
            v[k] = ((lane & 8) ? v[k + 8] : v[k]) + r;
        }
        #pragma unroll
        for (int k = 0; k < 4; k++) {
            float s = (lane & 4) ? v[k] : v[k + 4];
            float r = __shfl_xor_sync(0xffffffffu, s, 4);
            v[k] = ((lane & 4) ? v[k + 4] : v[k]) + r;
        }
        #pragma unroll
        for (int k = 0; k < 2; k++) {
            float s = (lane & 2) ? v[k] : v[k + 2];
            float r = __shfl_xor_sync(0xffffffffu, s, 2);
            v[k] = ((lane & 2) ? v[k + 2] : v[k]) + r;
        }
        {
            float s = (lane & 1) ? v[0] : v[1];
            float r = __shfl_xor_sync(0xffffffffu, s, 1);
            v[0] = ((lane & 1) ? v[1] : v[0]) + r;
        }
        vred[w * 32 + lane] = v[0];

        if (it > 0) {   // sp: merge batches then butterfly
            float s = (lane & 16) ? sp0 : sp1;
            float r = __shfl_xor_sync(0xffffffffu, s, 16);
            float sp = ((lane & 16) ? sp1 : sp0) + r;
            #pragma unroll
            for (int d = 8; d; d >>= 1)
                sp += __shfl_xor_sync(0xffffffffu, sp, d);
            if ((lane & 15) == 0) spred[w * 2 + (lane >> 4)] = sp;
        }
        __syncthreads();

        // --- final 18-way reduce + squash (warp 0: lanes 0-15 bb0, 16-31 bb1) ---
        if (tid < 32) {
            const int fb = tid >> 4;
            float O = 0.f;
            #pragma unroll
            for (int j = 0; j < NWARPS; j++) O += vred[j * 32 + tid];
            float S;
            if (it == 0) {
                S = (float)ND;
            } else {
                S = 0.f;
                #pragma unroll
                for (int j = 0; j < NWARPS; j++) S += spred[j * 2 + fb];
            }
            float t = O / S;
            float sq = t * t;
            #pragma unroll
            for (int d = 8; d; d >>= 1)
                sq += __shfl_xor_sync(0xffffffffu, sq, d);
            float scale = sq / ((1.f + sq) * sqrtf(sq + 1e-8f));
            float val = t * scale;
            outv[tid] = val;
            if (it == 2)
                out[((size_t)(c * BD + b0 + fb)) * OUTD + (tid & 15)] = val;
        }
        __syncthreads();
    }
}

extern "C" void kernel_launch(void* const* d_in, const int* in_sizes, int n_in,
                              void* d_out, int out_size)
{
    const float* x = (const float*)d_in[0];
    const float* W = (const float*)d_in[1];
    // defensive: identify by size (x: 1,179,648 ; W: 1,474,560)
    if (n_in >= 2 && in_sizes[0] == CCAP * ND * 8 * OUTD) {
        x = (const float*)d_in[1];
        W = (const float*)d_in[0];
    }
    float* out = (float*)d_out;

    const int ttotal = CCAP * 32 * ND;
    transpose_W_kernel<<<(ttotal + 255) / 256, 256>>>((const float4*)W);

    cudaFuncSetAttribute(caps_routing_kernel,
                         cudaFuncAttributeMaxDynamicSharedMemorySize, SMEM_BYTES);
    caps_routing_kernel<<<NBLOCKS, THREADS, SMEM_BYTES>>>(x, out);
}